// round 14
// baseline (speedup 1.0000x reference)
#include <cuda_runtime.h>
#include <cstdint>

#define BATCH 16384
#define NINP  256
#define HID   1024
#define NOUT  16
#define UH    32

// ---------------------------------------------------------------------------
// Device scratch (no runtime allocation allowed)
// ---------------------------------------------------------------------------
__device__ float g_h0[BATCH * HID];
__device__ float g_h1[BATCH * HID];
__device__ float g_x[BATCH * NINP];    // x pre-rounded to tf32 (main GEMM A)
__device__ float g_xt[NINP * BATCH];   // x^T, tf32-rounded (uni layer-1 input)
__device__ float g_w0t[HID * NINP];    // W0^T [HID][NINP], tf32-rounded
__device__ float g_w1t[HID * HID];     // W1^T, tf32-rounded
__device__ float g_w2t[NOUT * HID];    // W2^T [16][1024], tf32-rounded
__device__ float g_uw2t[NINP * UH * UH];    // per-feature w2^T [i][fo][fi], tf32
__device__ float g_uw3t[NINP * UH * NOUT];  // per-feature w3^T [i][fo][fi], tf32

// ---------------------------------------------------------------------------
// Helpers
// ---------------------------------------------------------------------------
__device__ __forceinline__ uint32_t smem_u32(const void* p) {
    uint32_t a;
    asm("{ .reg .u64 t; cvta.to.shared.u64 t, %1; cvt.u32.u64 %0, t; }"
        : "=r"(a) : "l"(p));
    return a;
}

// tf32 destination is a .b32 register (storage format), per PTX ISA.
__device__ __forceinline__ float to_tf32(float x) {
    uint32_t r;
    asm("cvt.rna.tf32.f32 %0, %1;" : "=r"(r) : "f"(x));
    return __uint_as_float(r);
}
__device__ __forceinline__ uint32_t tf32_bits(float x) {
    uint32_t r;
    asm("cvt.rna.tf32.f32 %0, %1;" : "=r"(r) : "f"(x));
    return r;
}

#define CP_ASYNC16(dst_u32, src_ptr) \
    asm volatile("cp.async.cg.shared.global [%0], [%1], 16;" \
        :: "r"(dst_u32), "l"(src_ptr))
#define CP_COMMIT() asm volatile("cp.async.commit_group;")
#define CP_WAIT(n)  asm volatile("cp.async.wait_group %0;" :: "n"(n))

__device__ __forceinline__ void mma_tf32(
    float& d0, float& d1, float& d2, float& d3,
    uint32_t a0, uint32_t a1, uint32_t a2, uint32_t a3,
    uint32_t b0, uint32_t b1)
{
    asm volatile(
        "mma.sync.aligned.m16n8k8.row.col.f32.tf32.tf32.f32 "
        "{%0,%1,%2,%3}, {%4,%5,%6,%7}, {%8,%9}, {%0,%1,%2,%3};"
        : "+f"(d0), "+f"(d1), "+f"(d2), "+f"(d3)
        : "r"(a0), "r"(a1), "r"(a2), "r"(a3), "r"(b0), "r"(b1));
}

// ---------------------------------------------------------------------------
// tf32 mma.sync GEMM (unchanged — measured 78us on GEMM1)
// ---------------------------------------------------------------------------
#define BM 128
#define BN 256
#define BK 32
#define ASTR 36
#define AS_FLOATS (BM * ASTR)
#define BS_FLOATS (BN * ASTR)
#define STG_FLOATS (AS_FLOATS + BS_FLOATS)
#define GEMM_SMEM ((BN + 2 * STG_FLOATS) * 4)

__global__ void __launch_bounds__(256, 1) mma_gemm(
    const float* __restrict__ A, const float* __restrict__ BT,
    const float* __restrict__ bias, float* __restrict__ C,
    int K, int Ntot, int relu, int roundout)
{
    extern __shared__ float sm[];
    float* bias_s = sm;
    float* stage0 = sm + BN;
    const uint32_t stage0_u32 = smem_u32(stage0);

    const int tid = threadIdx.x;
    const int lane = tid & 31;
    const int wid = tid >> 5;
    const int wr = wid >> 2;
    const int wc = wid & 3;
    const int m0 = blockIdx.y * BM;
    const int n0 = blockIdx.x * BN;

    if (tid < BN) bias_s[tid] = bias[n0 + tid];

    const int r = lane >> 2;
    const int c = lane & 3;

    float acc[4][8][4];
#pragma unroll
    for (int mt = 0; mt < 4; mt++)
#pragma unroll
        for (int nt = 0; nt < 8; nt++)
#pragma unroll
            for (int j = 0; j < 4; j++) acc[mt][nt][j] = 0.f;

    const int T = K / BK;

    auto issue = [&](int t) {
        const uint32_t su = stage0_u32 + (uint32_t)((t & 1) * STG_FLOATS) * 4u;
#pragma unroll
        for (int i = 0; i < 4; i++) {
            const int q = tid + i * 256;
            const int row = q >> 3, qq = q & 7;
            CP_ASYNC16(su + (uint32_t)(row * ASTR + qq * 4) * 4u,
                       A + (size_t)(m0 + row) * K + t * BK + qq * 4);
        }
        const uint32_t bu = su + AS_FLOATS * 4u;
#pragma unroll
        for (int i = 0; i < 8; i++) {
            const int q = tid + i * 256;
            const int row = q >> 3, qq = q & 7;
            CP_ASYNC16(bu + (uint32_t)(row * ASTR + qq * 4) * 4u,
                       BT + (size_t)(n0 + row) * K + t * BK + qq * 4);
        }
    };

    issue(0);
    CP_COMMIT();

    for (int t = 0; t < T; t++) {
        if (t + 1 < T) {
            issue(t + 1);
            CP_COMMIT();
            CP_WAIT(1);
        } else {
            CP_WAIT(0);
        }
        __syncthreads();

        const float* As = stage0 + (t & 1) * STG_FLOATS;
        const float* Bs = As + AS_FLOATS;

#pragma unroll
        for (int kk = 0; kk < 4; kk++) {
            uint32_t af[4][4];
#pragma unroll
            for (int mt = 0; mt < 4; mt++) {
                const int mb = wr * 64 + mt * 16;
                af[mt][0] = *(const uint32_t*)&As[(mb + r) * ASTR + kk * 8 + c];
                af[mt][1] = *(const uint32_t*)&As[(mb + r + 8) * ASTR + kk * 8 + c];
                af[mt][2] = *(const uint32_t*)&As[(mb + r) * ASTR + kk * 8 + c + 4];
                af[mt][3] = *(const uint32_t*)&As[(mb + r + 8) * ASTR + kk * 8 + c + 4];
            }
            uint32_t bf[8][2];
#pragma unroll
            for (int nt = 0; nt < 8; nt++) {
                const int bn = wc * 64 + nt * 8 + r;
                bf[nt][0] = *(const uint32_t*)&Bs[bn * ASTR + kk * 8 + c];
                bf[nt][1] = *(const uint32_t*)&Bs[bn * ASTR + kk * 8 + c + 4];
            }
#pragma unroll
            for (int mt = 0; mt < 4; mt++)
#pragma unroll
                for (int nt = 0; nt < 8; nt++)
                    mma_tf32(acc[mt][nt][0], acc[mt][nt][1],
                             acc[mt][nt][2], acc[mt][nt][3],
                             af[mt][0], af[mt][1], af[mt][2], af[mt][3],
                             bf[nt][0], bf[nt][1]);
        }
        __syncthreads();
    }

#pragma unroll
    for (int mt = 0; mt < 4; mt++) {
        const int row0 = m0 + wr * 64 + mt * 16 + r;
#pragma unroll
        for (int nt = 0; nt < 8; nt++) {
            const int col = n0 + wc * 64 + nt * 8 + c * 2;
            const float bx = bias_s[wc * 64 + nt * 8 + c * 2];
            const float by = bias_s[wc * 64 + nt * 8 + c * 2 + 1];
            float v0 = acc[mt][nt][0] + bx;
            float v1 = acc[mt][nt][1] + by;
            float v2 = acc[mt][nt][2] + bx;
            float v3 = acc[mt][nt][3] + by;
            if (relu) {
                v0 = fmaxf(v0, 0.f); v1 = fmaxf(v1, 0.f);
                v2 = fmaxf(v2, 0.f); v3 = fmaxf(v3, 0.f);
            }
            if (roundout) {
                v0 = to_tf32(v0); v1 = to_tf32(v1);
                v2 = to_tf32(v2); v3 = to_tf32(v3);
            }
            *(float2*)&C[(size_t)row0 * Ntot + col] = make_float2(v0, v1);
            *(float2*)&C[(size_t)(row0 + 8) * Ntot + col] = make_float2(v2, v3);
        }
    }
}

// ---------------------------------------------------------------------------
// Warp-direct K-split output GEMM: out += h1 @ W2 (+ b2 on split 0).
// Each warp: one m16 row-tile x one K=256 split; fragments via direct LDG
// (h1 line-efficient per 32-wide chunk; W2T L1-hot). No smem, no barriers.
// Grid 512 CTAs x 8 warps = 4096 warps; merge via atomicAdd into zeroed out.
// ---------------------------------------------------------------------------
#define OSPLIT 4
#define OKS (HID / OSPLIT)                 // 256

__global__ void __launch_bounds__(256) mma_out_ws(
    const float* __restrict__ Hin, const float* __restrict__ W2T,
    const float* __restrict__ b2, float* __restrict__ out)
{
    const int tid = threadIdx.x;
    const int lane = tid & 31;
    const int w = tid >> 5;
    const int r = lane >> 2;
    const int c = lane & 3;

    const int wg = blockIdx.x * 8 + w;
    const int rowtile = wg >> 2;           // 0..1023
    const int split = wg & 3;              // 0..3
    const int m0 = rowtile * 16;
    const int k0 = split * OKS;

    float acc[2][4];
#pragma unroll
    for (int nt = 0; nt < 2; nt++)
#pragma unroll
        for (int q = 0; q < 4; q++) acc[nt][q] = 0.f;

    const float* Ar0 = Hin + (size_t)(m0 + r) * HID + k0;
    const float* Ar8 = Hin + (size_t)(m0 + r + 8) * HID + k0;

    for (int ck = 0; ck < OKS / BK; ck++) {        // 8 chunks of 32
        const int kb = ck * BK;
#pragma unroll
        for (int kk = 0; kk < 4; kk++) {
            const int ko = kb + kk * 8 + c;
            const uint32_t a0 = __float_as_uint(Ar0[ko]);
            const uint32_t a1 = __float_as_uint(Ar8[ko]);
            const uint32_t a2 = __float_as_uint(Ar0[ko + 4]);
            const uint32_t a3 = __float_as_uint(Ar8[ko + 4]);
#pragma unroll
            for (int nt = 0; nt < 2; nt++) {
                const float* Bp = W2T + (size_t)(nt * 8 + r) * HID + k0 + ko - c + c;
                const uint32_t b0 = __float_as_uint(W2T[(size_t)(nt * 8 + r) * HID + k0 + kb + kk * 8 + c]);
                const uint32_t b1 = __float_as_uint(W2T[(size_t)(nt * 8 + r) * HID + k0 + kb + kk * 8 + c + 4]);
                (void)Bp;
                mma_tf32(acc[nt][0], acc[nt][1], acc[nt][2], acc[nt][3],
                         a0, a1, a2, a3, b0, b1);
            }
        }
    }

    // epilogue: split 0 adds bias; all splits atomically merge
#pragma unroll
    for (int nt = 0; nt < 2; nt++) {
        const int col = nt * 8 + 2 * c;
        float bx = 0.f, by = 0.f;
        if (split == 0) { bx = b2[col]; by = b2[col + 1]; }
        atomicAdd(&out[(size_t)(m0 + r) * NOUT + col],         acc[nt][0] + bx);
        atomicAdd(&out[(size_t)(m0 + r) * NOUT + col + 1],     acc[nt][1] + by);
        atomicAdd(&out[(size_t)(m0 + r + 8) * NOUT + col],     acc[nt][2] + bx);
        atomicAdd(&out[(size_t)(m0 + r + 8) * NOUT + col + 1], acc[nt][3] + by);
    }
}

// ---------------------------------------------------------------------------
// prep kernels
// ---------------------------------------------------------------------------
__global__ void __launch_bounds__(256) zero_out(float* __restrict__ u)
{
    u[blockIdx.x * 256 + threadIdx.x] = 0.f;
}

__global__ void __launch_bounds__(256) cvt_x(
    const float* __restrict__ in, float* __restrict__ outp, int n4)
{
    const int i = blockIdx.x * 256 + threadIdx.x;
    if (i < n4) {
        float4 v = ((const float4*)in)[i];
        v.x = to_tf32(v.x); v.y = to_tf32(v.y);
        v.z = to_tf32(v.z); v.w = to_tf32(v.w);
        ((float4*)outp)[i] = v;
    }
}

__global__ void __launch_bounds__(256) transpose_cvt(
    const float* __restrict__ W, float* __restrict__ WT, int K, int N)
{
    __shared__ float t[32][33];
    const int bx = blockIdx.x * 32;
    const int by = blockIdx.y * 32;
    const int x = threadIdx.x & 31;
    const int y = threadIdx.x >> 5;
#pragma unroll
    for (int i = 0; i < 32; i += 8)
        t[y + i][x] = to_tf32(W[(size_t)(by + y + i) * N + bx + x]);
    __syncthreads();
#pragma unroll
    for (int i = 0; i < 32; i += 8)
        WT[(size_t)(bx + y + i) * K + by + x] = t[x][y + i];
}

// W2 [1024][16] -> W2^T [16][1024] (tf32)
__global__ void __launch_bounds__(256) w2t_prep(
    const float* __restrict__ W2, float* __restrict__ W2T)
{
    const int idx = blockIdx.x * 256 + threadIdx.x;   // 16384 total
    const int k = idx >> 4, o = idx & 15;
    W2T[(size_t)o * HID + k] = to_tf32(W2[(size_t)k * NOUT + o]);
}

// Transpose per-feature uni weights to [i][fo][fi], tf32-rounded.
__global__ void __launch_bounds__(256) uni_w_prep(
    const float* __restrict__ uw2, const float* __restrict__ uw3,
    float* __restrict__ uw2t, float* __restrict__ uw3t)
{
    __shared__ float t2[32][33];
    __shared__ float t3[32][17];
    const int i = blockIdx.x;
    const int tid = threadIdx.x;

    {
        float4 v = ((const float4*)(uw2 + (size_t)i * UH * UH))[tid];
        const int fi = tid >> 3;
        const int fo = (tid & 7) * 4;
        t2[fi][fo + 0] = to_tf32(v.x);
        t2[fi][fo + 1] = to_tf32(v.y);
        t2[fi][fo + 2] = to_tf32(v.z);
        t2[fi][fo + 3] = to_tf32(v.w);
    }
    {
        float2 v = ((const float2*)(uw3 + (size_t)i * UH * NOUT))[tid];
        const int fi = tid >> 3;
        const int fo = (tid & 7) * 2;
        t3[fi][fo + 0] = to_tf32(v.x);
        t3[fi][fo + 1] = to_tf32(v.y);
    }
    __syncthreads();
    {
        const int fo = tid >> 3;
        const int fi = (tid & 7) * 4;
        float4 o;
        o.x = t2[fi + 0][fo]; o.y = t2[fi + 1][fo];
        o.z = t2[fi + 2][fo]; o.w = t2[fi + 3][fo];
        ((float4*)(uw2t + (size_t)i * UH * UH))[tid] = o;
    }
    {
        const int fo = tid >> 4;
        const int fi = (tid & 15) * 2;
        float2 o;
        o.x = t3[fi + 0][fo]; o.y = t3[fi + 1][fo];
        ((float2*)(uw3t + (size_t)i * NOUT * UH))[tid] = o;
    }
}

// ---------------------------------------------------------------------------
// Register-resident uni MLPs (R12-measured 205us); merges directly into out.
// ---------------------------------------------------------------------------
__global__ void __launch_bounds__(256) uni_reg(
    const float* __restrict__ xt,
    const float* __restrict__ uw1, const float* __restrict__ ub1,
    const float* __restrict__ uw2t, const float* __restrict__ ub2,
    const float* __restrict__ uw3t, const float* __restrict__ ub3,
    float* __restrict__ uni_out)
{
    __shared__ float acc_s[256 * 17];

    const int tid = threadIdx.x;
    const int lane = tid & 31;
    const int w = tid >> 5;
    const int r = lane >> 2;
    const int c = lane & 3;
    const int i = blockIdx.y * 8 + w;          // this warp's feature
    const int rowbase = blockIdx.x * 256;

#pragma unroll
    for (int q = 0; q < 17; q++) acc_s[q * 256 + tid] = 0.f;
    __syncthreads();

    uint32_t w2f[4][4][2];
#pragma unroll
    for (int kk = 0; kk < 4; kk++)
#pragma unroll
        for (int nt = 0; nt < 4; nt++) {
            const float* p = uw2t + (size_t)i * 1024 + (nt * 8 + r) * 32 + kk * 8 + c;
            w2f[kk][nt][0] = __float_as_uint(p[0]);
            w2f[kk][nt][1] = __float_as_uint(p[4]);
        }
    uint32_t w3f[4][2][2];
#pragma unroll
    for (int kk = 0; kk < 4; kk++)
#pragma unroll
        for (int nt = 0; nt < 2; nt++) {
            const float* p = uw3t + (size_t)i * 512 + (nt * 8 + r) * 32 + kk * 8 + c;
            w3f[kk][nt][0] = __float_as_uint(p[0]);
            w3f[kk][nt][1] = __float_as_uint(p[4]);
        }
    float w1v[8], b1v[8];
#pragma unroll
    for (int kk = 0; kk < 4; kk++) {
        w1v[kk * 2 + 0] = uw1[i * 32 + kk * 8 + c];
        w1v[kk * 2 + 1] = uw1[i * 32 + kk * 8 + c + 4];
        b1v[kk * 2 + 0] = ub1[i * 32 + kk * 8 + c];
        b1v[kk * 2 + 1] = ub1[i * 32 + kk * 8 + c + 4];
    }
    float b2v[8];
#pragma unroll
    for (int nt = 0; nt < 4; nt++) {
        b2v[nt * 2 + 0] = ub2[i * 32 + nt * 8 + 2 * c];
        b2v[nt * 2 + 1] = ub2[i * 32 + nt * 8 + 2 * c + 1];
    }
    float b3v[4];
#pragma unroll
    for (int nt = 0; nt < 2; nt++) {
        b3v[nt * 2 + 0] = ub3[i * 16 + nt * 8 + 2 * c];
        b3v[nt * 2 + 1] = ub3[i * 16 + nt * 8 + 2 * c + 1];
    }

    const int L0 = r * 4 + (c >> 1);
    const bool odd = (c & 1) != 0;

    for (int t = 0; t < 16; t++) {
        const int rb = rowbase + t * 16;

        float xl = 0.f;
        if (lane < 16) xl = xt[(size_t)i * BATCH + rb + lane];
        const float xr0 = __shfl_sync(0xffffffffu, xl, r);
        const float xr8 = __shfl_sync(0xffffffffu, xl, r + 8);

        uint32_t h1f[4][4];
#pragma unroll
        for (int kk = 0; kk < 4; kk++) {
            h1f[kk][0] = tf32_bits(fmaxf(fmaf(xr0, w1v[kk * 2 + 0], b1v[kk * 2 + 0]), 0.f));
            h1f[kk][1] = tf32_bits(fmaxf(fmaf(xr8, w1v[kk * 2 + 0], b1v[kk * 2 + 0]), 0.f));
            h1f[kk][2] = tf32_bits(fmaxf(fmaf(xr0, w1v[kk * 2 + 1], b1v[kk * 2 + 1]), 0.f));
            h1f[kk][3] = tf32_bits(fmaxf(fmaf(xr8, w1v[kk * 2 + 1], b1v[kk * 2 + 1]), 0.f));
        }

        float c2[4][4];
#pragma unroll
        for (int nt = 0; nt < 4; nt++)
#pragma unroll
            for (int q = 0; q < 4; q++) c2[nt][q] = 0.f;
#pragma unroll
        for (int kk = 0; kk < 4; kk++)
#pragma unroll
            for (int nt = 0; nt < 4; nt++)
                mma_tf32(c2[nt][0], c2[nt][1], c2[nt][2], c2[nt][3],
                         h1f[kk][0], h1f[kk][1], h1f[kk][2], h1f[kk][3],
                         w2f[kk][nt][0], w2f[kk][nt][1]);

        uint32_t h2r[4][4];
#pragma unroll
        for (int nt = 0; nt < 4; nt++) {
            h2r[nt][0] = tf32_bits(fmaxf(c2[nt][0] + b2v[nt * 2 + 0], 0.f));
            h2r[nt][1] = tf32_bits(fmaxf(c2[nt][1] + b2v[nt * 2 + 1], 0.f));
            h2r[nt][2] = tf32_bits(fmaxf(c2[nt][2] + b2v[nt * 2 + 0], 0.f));
            h2r[nt][3] = tf32_bits(fmaxf(c2[nt][3] + b2v[nt * 2 + 1], 0.f));
        }

        uint32_t h2a[4][4];
#pragma unroll
        for (int kk = 0; kk < 4; kk++) {
            const uint32_t e0 = __shfl_sync(0xffffffffu, h2r[kk][0], L0);
            const uint32_t o0 = __shfl_sync(0xffffffffu, h2r[kk][1], L0);
            const uint32_t e8 = __shfl_sync(0xffffffffu, h2r[kk][2], L0);
            const uint32_t o8 = __shfl_sync(0xffffffffu, h2r[kk][3], L0);
            const uint32_t f0 = __shfl_sync(0xffffffffu, h2r[kk][0], L0 + 2);
            const uint32_t p0 = __shfl_sync(0xffffffffu, h2r[kk][1], L0 + 2);
            const uint32_t f8 = __shfl_sync(0xffffffffu, h2r[kk][2], L0 + 2);
            const uint32_t p8 = __shfl_sync(0xffffffffu, h2r[kk][3], L0 + 2);
            h2a[kk][0] = odd ? o0 : e0;
            h2a[kk][1] = odd ? o8 : e8;
            h2a[kk][2] = odd ? p0 : f0;
            h2a[kk][3] = odd ? p8 : f8;
        }

        float u[2][4];
#pragma unroll
        for (int nt = 0; nt < 2; nt++) {
            u[nt][0] = b3v[nt * 2 + 0];
            u[nt][1] = b3v[nt * 2 + 1];
            u[nt][2] = b3v[nt * 2 + 0];
            u[nt][3] = b3v[nt * 2 + 1];
        }
#pragma unroll
        for (int kk = 0; kk < 4; kk++)
#pragma unroll
            for (int nt = 0; nt < 2; nt++)
                mma_tf32(u[nt][0], u[nt][1], u[nt][2], u[nt][3],
                         h2a[kk][0], h2a[kk][1], h2a[kk][2], h2a[kk][3],
                         w3f[kk][nt][0], w3f[kk][nt][1]);

        const int lr0 = t * 16 + r;
#pragma unroll
        for (int nt = 0; nt < 2; nt++) {
            const int col = nt * 8 + 2 * c;
            atomicAdd(&acc_s[lr0 * 17 + col],           u[nt][0]);
            atomicAdd(&acc_s[lr0 * 17 + col + 1],       u[nt][1]);
            atomicAdd(&acc_s[(lr0 + 8) * 17 + col],     u[nt][2]);
            atomicAdd(&acc_s[(lr0 + 8) * 17 + col + 1], u[nt][3]);
        }
    }

    __syncthreads();
#pragma unroll
    for (int q = 0; q < 16; q++) {
        const int idx = q * 256 + tid;
        const int row = idx >> 4, col = idx & 15;
        atomicAdd(&uni_out[(size_t)(rowbase + row) * NOUT + col],
                  acc_s[row * 17 + col]);
    }
}

// ---------------------------------------------------------------------------
extern "C" void kernel_launch(void* const* d_in, const int* in_sizes, int n_in,
                              void* d_out, int out_size)
{
    const float* x   = (const float*)d_in[0];
    const float* W0  = (const float*)d_in[1];
    const float* b0  = (const float*)d_in[2];
    const float* W1  = (const float*)d_in[3];
    const float* b1  = (const float*)d_in[4];
    const float* W2  = (const float*)d_in[5];
    const float* b2  = (const float*)d_in[6];
    const float* uw1 = (const float*)d_in[7];
    const float* ub1 = (const float*)d_in[8];
    const float* uw2 = (const float*)d_in[9];
    const float* ub2 = (const float*)d_in[10];
    const float* uw3 = (const float*)d_in[11];
    const float* ub3 = (const float*)d_in[12];
    float* out = (float*)d_out;

    float *h0, *h1, *xr, *xt, *w0t, *w1t, *w2t, *uw2t, *uw3t;
    cudaGetSymbolAddress((void**)&h0, g_h0);
    cudaGetSymbolAddress((void**)&h1, g_h1);
    cudaGetSymbolAddress((void**)&xr, g_x);
    cudaGetSymbolAddress((void**)&xt, g_xt);
    cudaGetSymbolAddress((void**)&w0t, g_w0t);
    cudaGetSymbolAddress((void**)&w1t, g_w1t);
    cudaGetSymbolAddress((void**)&w2t, g_w2t);
    cudaGetSymbolAddress((void**)&uw2t, g_uw2t);
    cudaGetSymbolAddress((void**)&uw3t, g_uw3t);

    cudaFuncSetAttribute(mma_gemm, cudaFuncAttributeMaxDynamicSharedMemorySize, GEMM_SMEM);

    // uni path first (slot 3 = profiler capture window)
    uni_w_prep<<<NINP, 256>>>(uw2, uw3, uw2t, uw3t);                     // 0
    {
        dim3 gx(NINP / 32, BATCH / 32);
        transpose_cvt<<<gx, 256>>>(x, xt, BATCH, NINP);                  // 1
    }
    zero_out<<<BATCH * NOUT / 256, 256>>>(out);                          // 2
    {
        dim3 grid(BATCH / 256, NINP / 8);
        uni_reg<<<grid, 256>>>(xt, uw1, ub1, uw2t, ub2, uw3t, ub3, out); // 3
    }

    // main MLP
    cvt_x<<<(BATCH * NINP / 4 + 255) / 256, 256>>>(x, xr, BATCH * NINP / 4);
    {
        dim3 g0(HID / 32, NINP / 32);
        transpose_cvt<<<g0, 256>>>(W0, w0t, NINP, HID);
        dim3 g1(HID / 32, HID / 32);
        transpose_cvt<<<g1, 256>>>(W1, w1t, HID, HID);
    }
    w2t_prep<<<NOUT * HID / 256, 256>>>(W2, w2t);
    {
        dim3 grid(HID / BN, BATCH / BM);
        mma_gemm<<<grid, 256, GEMM_SMEM>>>(xr, w0t, b0, h0, NINP, HID, 1, 1);
        // roundout=1: h1 feeds the tf32 mma_out_ws
        mma_gemm<<<grid, 256, GEMM_SMEM>>>(h0, w1t, b1, h1, HID, HID, 1, 1);
    }

    // out += h1 @ W2 (+ b2 on split 0); uni already merged
    mma_out_ws<<<(BATCH / 16) * OSPLIT / 8, 256>>>(h1, w2t, b2, out);
}

// round 16
// speedup vs baseline: 1.0515x; 1.0515x over previous
#include <cuda_runtime.h>
#include <cstdint>

#define BATCH 16384
#define NINP  256
#define HID   1024
#define NOUT  16
#define UH    32

// ---------------------------------------------------------------------------
// Device scratch (no runtime allocation allowed)
// ---------------------------------------------------------------------------
__device__ float g_h0[BATCH * HID];
__device__ float g_x[BATCH * NINP];    // x pre-rounded to tf32 (main GEMM A)
__device__ float g_xt[NINP * BATCH];   // x^T, tf32-rounded (uni layer-1 input)
__device__ float g_w0t[HID * NINP];    // W0^T [HID][NINP], tf32-rounded
__device__ float g_w1t[HID * HID];     // W1^T, tf32-rounded
__device__ float g_w2t[NOUT * HID];    // W2^T [16][1024], tf32-rounded
__device__ float g_uw2t[NINP * UH * UH];    // per-feature w2^T [i][fo][fi], tf32
__device__ float g_uw3t[NINP * UH * NOUT];  // per-feature w3^T [i][fo][fi], tf32

// ---------------------------------------------------------------------------
// Helpers
// ---------------------------------------------------------------------------
__device__ __forceinline__ uint32_t smem_u32(const void* p) {
    uint32_t a;
    asm("{ .reg .u64 t; cvta.to.shared.u64 t, %1; cvt.u32.u64 %0, t; }"
        : "=r"(a) : "l"(p));
    return a;
}

// tf32 destination is a .b32 register (storage format), per PTX ISA.
__device__ __forceinline__ float to_tf32(float x) {
    uint32_t r;
    asm("cvt.rna.tf32.f32 %0, %1;" : "=r"(r) : "f"(x));
    return __uint_as_float(r);
}
__device__ __forceinline__ uint32_t tf32_bits(float x) {
    uint32_t r;
    asm("cvt.rna.tf32.f32 %0, %1;" : "=r"(r) : "f"(x));
    return r;
}

#define CP_ASYNC16(dst_u32, src_ptr) \
    asm volatile("cp.async.cg.shared.global [%0], [%1], 16;" \
        :: "r"(dst_u32), "l"(src_ptr))
#define CP_COMMIT() asm volatile("cp.async.commit_group;")
#define CP_WAIT(n)  asm volatile("cp.async.wait_group %0;" :: "n"(n))

__device__ __forceinline__ void mma_tf32(
    float& d0, float& d1, float& d2, float& d3,
    uint32_t a0, uint32_t a1, uint32_t a2, uint32_t a3,
    uint32_t b0, uint32_t b1)
{
    asm volatile(
        "mma.sync.aligned.m16n8k8.row.col.f32.tf32.tf32.f32 "
        "{%0,%1,%2,%3}, {%4,%5,%6,%7}, {%8,%9}, {%0,%1,%2,%3};"
        : "+f"(d0), "+f"(d1), "+f"(d2), "+f"(d3)
        : "r"(a0), "r"(a1), "r"(a2), "r"(a3), "r"(b0), "r"(b1));
}

// ---------------------------------------------------------------------------
// Shared GEMM config
// ---------------------------------------------------------------------------
#define BM 128
#define BN 256
#define BK 32
#define ASTR 36
#define AS_FLOATS (BM * ASTR)
#define BS_FLOATS (BN * ASTR)
#define STG_FLOATS (AS_FLOATS + BS_FLOATS)
#define GEMM_SMEM ((BN + 2 * STG_FLOATS) * 4)

// ---------------------------------------------------------------------------
// tf32 mma.sync GEMM (used for GEMM0)
// ---------------------------------------------------------------------------
__global__ void __launch_bounds__(256, 1) mma_gemm(
    const float* __restrict__ A, const float* __restrict__ BT,
    const float* __restrict__ bias, float* __restrict__ C,
    int K, int Ntot, int relu, int roundout)
{
    extern __shared__ float sm[];
    float* bias_s = sm;
    float* stage0 = sm + BN;
    const uint32_t stage0_u32 = smem_u32(stage0);

    const int tid = threadIdx.x;
    const int lane = tid & 31;
    const int wid = tid >> 5;
    const int wr = wid >> 2;
    const int wc = wid & 3;
    const int m0 = blockIdx.y * BM;
    const int n0 = blockIdx.x * BN;

    if (tid < BN) bias_s[tid] = bias[n0 + tid];

    const int r = lane >> 2;
    const int c = lane & 3;

    float acc[4][8][4];
#pragma unroll
    for (int mt = 0; mt < 4; mt++)
#pragma unroll
        for (int nt = 0; nt < 8; nt++)
#pragma unroll
            for (int j = 0; j < 4; j++) acc[mt][nt][j] = 0.f;

    const int T = K / BK;

    auto issue = [&](int t) {
        const uint32_t su = stage0_u32 + (uint32_t)((t & 1) * STG_FLOATS) * 4u;
#pragma unroll
        for (int i = 0; i < 4; i++) {
            const int q = tid + i * 256;
            const int row = q >> 3, qq = q & 7;
            CP_ASYNC16(su + (uint32_t)(row * ASTR + qq * 4) * 4u,
                       A + (size_t)(m0 + row) * K + t * BK + qq * 4);
        }
        const uint32_t bu = su + AS_FLOATS * 4u;
#pragma unroll
        for (int i = 0; i < 8; i++) {
            const int q = tid + i * 256;
            const int row = q >> 3, qq = q & 7;
            CP_ASYNC16(bu + (uint32_t)(row * ASTR + qq * 4) * 4u,
                       BT + (size_t)(n0 + row) * K + t * BK + qq * 4);
        }
    };

    issue(0);
    CP_COMMIT();

    for (int t = 0; t < T; t++) {
        if (t + 1 < T) {
            issue(t + 1);
            CP_COMMIT();
            CP_WAIT(1);
        } else {
            CP_WAIT(0);
        }
        __syncthreads();

        const float* As = stage0 + (t & 1) * STG_FLOATS;
        const float* Bs = As + AS_FLOATS;

#pragma unroll
        for (int kk = 0; kk < 4; kk++) {
            uint32_t af[4][4];
#pragma unroll
            for (int mt = 0; mt < 4; mt++) {
                const int mb = wr * 64 + mt * 16;
                af[mt][0] = *(const uint32_t*)&As[(mb + r) * ASTR + kk * 8 + c];
                af[mt][1] = *(const uint32_t*)&As[(mb + r + 8) * ASTR + kk * 8 + c];
                af[mt][2] = *(const uint32_t*)&As[(mb + r) * ASTR + kk * 8 + c + 4];
                af[mt][3] = *(const uint32_t*)&As[(mb + r + 8) * ASTR + kk * 8 + c + 4];
            }
            uint32_t bf[8][2];
#pragma unroll
            for (int nt = 0; nt < 8; nt++) {
                const int bn = wc * 64 + nt * 8 + r;
                bf[nt][0] = *(const uint32_t*)&Bs[bn * ASTR + kk * 8 + c];
                bf[nt][1] = *(const uint32_t*)&Bs[bn * ASTR + kk * 8 + c + 4];
            }
#pragma unroll
            for (int mt = 0; mt < 4; mt++)
#pragma unroll
                for (int nt = 0; nt < 8; nt++)
                    mma_tf32(acc[mt][nt][0], acc[mt][nt][1],
                             acc[mt][nt][2], acc[mt][nt][3],
                             af[mt][0], af[mt][1], af[mt][2], af[mt][3],
                             bf[nt][0], bf[nt][1]);
        }
        __syncthreads();
    }

#pragma unroll
    for (int mt = 0; mt < 4; mt++) {
        const int row0 = m0 + wr * 64 + mt * 16 + r;
#pragma unroll
        for (int nt = 0; nt < 8; nt++) {
            const int col = n0 + wc * 64 + nt * 8 + c * 2;
            const float bx = bias_s[wc * 64 + nt * 8 + c * 2];
            const float by = bias_s[wc * 64 + nt * 8 + c * 2 + 1];
            float v0 = acc[mt][nt][0] + bx;
            float v1 = acc[mt][nt][1] + by;
            float v2 = acc[mt][nt][2] + bx;
            float v3 = acc[mt][nt][3] + by;
            if (relu) {
                v0 = fmaxf(v0, 0.f); v1 = fmaxf(v1, 0.f);
                v2 = fmaxf(v2, 0.f); v3 = fmaxf(v3, 0.f);
            }
            if (roundout) {
                v0 = to_tf32(v0); v1 = to_tf32(v1);
                v2 = to_tf32(v2); v3 = to_tf32(v3);
            }
            *(float2*)&C[(size_t)row0 * Ntot + col] = make_float2(v0, v1);
            *(float2*)&C[(size_t)(row0 + 8) * Ntot + col] = make_float2(v2, v3);
        }
    }
}

// ---------------------------------------------------------------------------
// GEMM1 with FUSED output layer: h1 = relu(h0 @ W1 + b1) stays in registers;
// epilogue contracts it against W2 (out += h1_tile @ W2 slice). h1 never
// touches global memory; the third kernel is deleted.
// ---------------------------------------------------------------------------
__global__ void __launch_bounds__(256, 1) mma_gemm_out(
    const float* __restrict__ A, const float* __restrict__ BT,
    const float* __restrict__ bias, const float* __restrict__ W2T,
    const float* __restrict__ b2, float* __restrict__ out)
{
    extern __shared__ float sm[];
    float* bias_s = sm;
    float* stage0 = sm + BN;
    const uint32_t stage0_u32 = smem_u32(stage0);

    const int tid = threadIdx.x;
    const int lane = tid & 31;
    const int wid = tid >> 5;
    const int wr = wid >> 2;
    const int wc = wid & 3;
    const int m0 = blockIdx.y * BM;
    const int n0 = blockIdx.x * BN;
    const int K = HID;

    if (tid < BN) bias_s[tid] = bias[n0 + tid];

    const int r = lane >> 2;
    const int c = lane & 3;

    float acc[4][8][4];
#pragma unroll
    for (int mt = 0; mt < 4; mt++)
#pragma unroll
        for (int nt = 0; nt < 8; nt++)
#pragma unroll
            for (int j = 0; j < 4; j++) acc[mt][nt][j] = 0.f;

    const int T = K / BK;

    auto issue = [&](int t) {
        const uint32_t su = stage0_u32 + (uint32_t)((t & 1) * STG_FLOATS) * 4u;
#pragma unroll
        for (int i = 0; i < 4; i++) {
            const int q = tid + i * 256;
            const int row = q >> 3, qq = q & 7;
            CP_ASYNC16(su + (uint32_t)(row * ASTR + qq * 4) * 4u,
                       A + (size_t)(m0 + row) * K + t * BK + qq * 4);
        }
        const uint32_t bu = su + AS_FLOATS * 4u;
#pragma unroll
        for (int i = 0; i < 8; i++) {
            const int q = tid + i * 256;
            const int row = q >> 3, qq = q & 7;
            CP_ASYNC16(bu + (uint32_t)(row * ASTR + qq * 4) * 4u,
                       BT + (size_t)(n0 + row) * K + t * BK + qq * 4);
        }
    };

    issue(0);
    CP_COMMIT();

    for (int t = 0; t < T; t++) {
        if (t + 1 < T) {
            issue(t + 1);
            CP_COMMIT();
            CP_WAIT(1);
        } else {
            CP_WAIT(0);
        }
        __syncthreads();

        const float* As = stage0 + (t & 1) * STG_FLOATS;
        const float* Bs = As + AS_FLOATS;

#pragma unroll
        for (int kk = 0; kk < 4; kk++) {
            uint32_t af[4][4];
#pragma unroll
            for (int mt = 0; mt < 4; mt++) {
                const int mb = wr * 64 + mt * 16;
                af[mt][0] = *(const uint32_t*)&As[(mb + r) * ASTR + kk * 8 + c];
                af[mt][1] = *(const uint32_t*)&As[(mb + r + 8) * ASTR + kk * 8 + c];
                af[mt][2] = *(const uint32_t*)&As[(mb + r) * ASTR + kk * 8 + c + 4];
                af[mt][3] = *(const uint32_t*)&As[(mb + r + 8) * ASTR + kk * 8 + c + 4];
            }
            uint32_t bf[8][2];
#pragma unroll
            for (int nt = 0; nt < 8; nt++) {
                const int bn = wc * 64 + nt * 8 + r;
                bf[nt][0] = *(const uint32_t*)&Bs[bn * ASTR + kk * 8 + c];
                bf[nt][1] = *(const uint32_t*)&Bs[bn * ASTR + kk * 8 + c + 4];
            }
#pragma unroll
            for (int mt = 0; mt < 4; mt++)
#pragma unroll
                for (int nt = 0; nt < 8; nt++)
                    mma_tf32(acc[mt][nt][0], acc[mt][nt][1],
                             acc[mt][nt][2], acc[mt][nt][3],
                             af[mt][0], af[mt][1], af[mt][2], af[mt][3],
                             bf[nt][0], bf[nt][1]);
        }
        __syncthreads();
    }

    // ---- fused output epilogue ----
    float* ws = stage0 + wid * (16 * 68);            // per-warp 16x68 strip
    const int wcol0 = n0 + wc * 64;                  // warp's K-range in W2
    const bool addb = (blockIdx.x == 0 && wc == 0);

#pragma unroll
    for (int mt = 0; mt < 4; mt++) {
        // stage relu'd tf32 h1 tile (rows r/r+8, 64 cols)
#pragma unroll
        for (int nt = 0; nt < 8; nt++) {
            const int j = nt * 8 + 2 * c;
            const float bx = bias_s[wc * 64 + j];
            const float by = bias_s[wc * 64 + j + 1];
            const float v0 = to_tf32(fmaxf(acc[mt][nt][0] + bx, 0.f));
            const float v1 = to_tf32(fmaxf(acc[mt][nt][1] + by, 0.f));
            const float v2 = to_tf32(fmaxf(acc[mt][nt][2] + bx, 0.f));
            const float v3 = to_tf32(fmaxf(acc[mt][nt][3] + by, 0.f));
            *(float2*)&ws[r * 68 + j] = make_float2(v0, v1);
            *(float2*)&ws[(r + 8) * 68 + j] = make_float2(v2, v3);
        }
        __syncwarp(0xffffffffu);

        float po[2][4];
#pragma unroll
        for (int nt2 = 0; nt2 < 2; nt2++)
#pragma unroll
            for (int q = 0; q < 4; q++) po[nt2][q] = 0.f;

#pragma unroll
        for (int kk = 0; kk < 8; kk++) {
            const uint32_t a0 = *(const uint32_t*)&ws[r * 68 + kk * 8 + c];
            const uint32_t a1 = *(const uint32_t*)&ws[(r + 8) * 68 + kk * 8 + c];
            const uint32_t a2 = *(const uint32_t*)&ws[r * 68 + kk * 8 + c + 4];
            const uint32_t a3 = *(const uint32_t*)&ws[(r + 8) * 68 + kk * 8 + c + 4];
#pragma unroll
            for (int nt2 = 0; nt2 < 2; nt2++) {
                const uint32_t b0 = __float_as_uint(
                    W2T[(size_t)(nt2 * 8 + r) * HID + wcol0 + kk * 8 + c]);
                const uint32_t b1 = __float_as_uint(
                    W2T[(size_t)(nt2 * 8 + r) * HID + wcol0 + kk * 8 + c + 4]);
                mma_tf32(po[nt2][0], po[nt2][1], po[nt2][2], po[nt2][3],
                         a0, a1, a2, a3, b0, b1);
            }
        }
        __syncwarp(0xffffffffu);     // strip reused next mt

        const int row0 = m0 + wr * 64 + mt * 16 + r;
#pragma unroll
        for (int nt2 = 0; nt2 < 2; nt2++) {
            const int col = nt2 * 8 + 2 * c;
            const float bx = addb ? b2[col] : 0.f;
            const float by = addb ? b2[col + 1] : 0.f;
            atomicAdd(&out[(size_t)row0 * NOUT + col],           po[nt2][0] + bx);
            atomicAdd(&out[(size_t)row0 * NOUT + col + 1],       po[nt2][1] + by);
            atomicAdd(&out[(size_t)(row0 + 8) * NOUT + col],     po[nt2][2] + bx);
            atomicAdd(&out[(size_t)(row0 + 8) * NOUT + col + 1], po[nt2][3] + by);
        }
    }
}

// ---------------------------------------------------------------------------
// prep kernels
// ---------------------------------------------------------------------------
__global__ void __launch_bounds__(256) zero_out(float* __restrict__ u)
{
    u[blockIdx.x * 256 + threadIdx.x] = 0.f;
}

__global__ void __launch_bounds__(256) cvt_x(
    const float* __restrict__ in, float* __restrict__ outp, int n4)
{
    const int i = blockIdx.x * 256 + threadIdx.x;
    if (i < n4) {
        float4 v = ((const float4*)in)[i];
        v.x = to_tf32(v.x); v.y = to_tf32(v.y);
        v.z = to_tf32(v.z); v.w = to_tf32(v.w);
        ((float4*)outp)[i] = v;
    }
}

__global__ void __launch_bounds__(256) transpose_cvt(
    const float* __restrict__ W, float* __restrict__ WT, int K, int N)
{
    __shared__ float t[32][33];
    const int bx = blockIdx.x * 32;
    const int by = blockIdx.y * 32;
    const int x = threadIdx.x & 31;
    const int y = threadIdx.x >> 5;
#pragma unroll
    for (int i = 0; i < 32; i += 8)
        t[y + i][x] = to_tf32(W[(size_t)(by + y + i) * N + bx + x]);
    __syncthreads();
#pragma unroll
    for (int i = 0; i < 32; i += 8)
        WT[(size_t)(bx + y + i) * K + by + x] = t[x][y + i];
}

// W2 [1024][16] -> W2^T [16][1024] (tf32)
__global__ void __launch_bounds__(256) w2t_prep(
    const float* __restrict__ W2, float* __restrict__ W2T)
{
    const int idx = blockIdx.x * 256 + threadIdx.x;
    const int k = idx >> 4, o = idx & 15;
    W2T[(size_t)o * HID + k] = to_tf32(W2[(size_t)k * NOUT + o]);
}

// Transpose per-feature uni weights to [i][fo][fi], tf32-rounded.
__global__ void __launch_bounds__(256) uni_w_prep(
    const float* __restrict__ uw2, const float* __restrict__ uw3,
    float* __restrict__ uw2t, float* __restrict__ uw3t)
{
    __shared__ float t2[32][33];
    __shared__ float t3[32][17];
    const int i = blockIdx.x;
    const int tid = threadIdx.x;

    {
        float4 v = ((const float4*)(uw2 + (size_t)i * UH * UH))[tid];
        const int fi = tid >> 3;
        const int fo = (tid & 7) * 4;
        t2[fi][fo + 0] = to_tf32(v.x);
        t2[fi][fo + 1] = to_tf32(v.y);
        t2[fi][fo + 2] = to_tf32(v.z);
        t2[fi][fo + 3] = to_tf32(v.w);
    }
    {
        float2 v = ((const float2*)(uw3 + (size_t)i * UH * NOUT))[tid];
        const int fi = tid >> 3;
        const int fo = (tid & 7) * 2;
        t3[fi][fo + 0] = to_tf32(v.x);
        t3[fi][fo + 1] = to_tf32(v.y);
    }
    __syncthreads();
    {
        const int fo = tid >> 3;
        const int fi = (tid & 7) * 4;
        float4 o;
        o.x = t2[fi + 0][fo]; o.y = t2[fi + 1][fo];
        o.z = t2[fi + 2][fo]; o.w = t2[fi + 3][fo];
        ((float4*)(uw2t + (size_t)i * UH * UH))[tid] = o;
    }
    {
        const int fo = tid >> 4;
        const int fi = (tid & 15) * 2;
        float2 o;
        o.x = t3[fi + 0][fo]; o.y = t3[fi + 1][fo];
        ((float2*)(uw3t + (size_t)i * NOUT * UH))[tid] = o;
    }
}

// ---------------------------------------------------------------------------
// Register-resident uni MLPs (measured 209.7us); merges directly into out.
// ---------------------------------------------------------------------------
__global__ void __launch_bounds__(256) uni_reg(
    const float* __restrict__ xt,
    const float* __restrict__ uw1, const float* __restrict__ ub1,
    const float* __restrict__ uw2t, const float* __restrict__ ub2,
    const float* __restrict__ uw3t, const float* __restrict__ ub3,
    float* __restrict__ uni_out)
{
    __shared__ float acc_s[256 * 17];

    const int tid = threadIdx.x;
    const int lane = tid & 31;
    const int w = tid >> 5;
    const int r = lane >> 2;
    const int c = lane & 3;
    const int i = blockIdx.y * 8 + w;
    const int rowbase = blockIdx.x * 256;

#pragma unroll
    for (int q = 0; q < 17; q++) acc_s[q * 256 + tid] = 0.f;
    __syncthreads();

    uint32_t w2f[4][4][2];
#pragma unroll
    for (int kk = 0; kk < 4; kk++)
#pragma unroll
        for (int nt = 0; nt < 4; nt++) {
            const float* p = uw2t + (size_t)i * 1024 + (nt * 8 + r) * 32 + kk * 8 + c;
            w2f[kk][nt][0] = __float_as_uint(p[0]);
            w2f[kk][nt][1] = __float_as_uint(p[4]);
        }
    uint32_t w3f[4][2][2];
#pragma unroll
    for (int kk = 0; kk < 4; kk++)
#pragma unroll
        for (int nt = 0; nt < 2; nt++) {
            const float* p = uw3t + (size_t)i * 512 + (nt * 8 + r) * 32 + kk * 8 + c;
            w3f[kk][nt][0] = __float_as_uint(p[0]);
            w3f[kk][nt][1] = __float_as_uint(p[4]);
        }
    float w1v[8], b1v[8];
#pragma unroll
    for (int kk = 0; kk < 4; kk++) {
        w1v[kk * 2 + 0] = uw1[i * 32 + kk * 8 + c];
        w1v[kk * 2 + 1] = uw1[i * 32 + kk * 8 + c + 4];
        b1v[kk * 2 + 0] = ub1[i * 32 + kk * 8 + c];
        b1v[kk * 2 + 1] = ub1[i * 32 + kk * 8 + c + 4];
    }
    float b2v[8];
#pragma unroll
    for (int nt = 0; nt < 4; nt++) {
        b2v[nt * 2 + 0] = ub2[i * 32 + nt * 8 + 2 * c];
        b2v[nt * 2 + 1] = ub2[i * 32 + nt * 8 + 2 * c + 1];
    }
    float b3v[4];
#pragma unroll
    for (int nt = 0; nt < 2; nt++) {
        b3v[nt * 2 + 0] = ub3[i * 16 + nt * 8 + 2 * c];
        b3v[nt * 2 + 1] = ub3[i * 16 + nt * 8 + 2 * c + 1];
    }

    const int L0 = r * 4 + (c >> 1);
    const bool odd = (c & 1) != 0;

    for (int t = 0; t < 16; t++) {
        const int rb = rowbase + t * 16;

        float xl = 0.f;
        if (lane < 16) xl = xt[(size_t)i * BATCH + rb + lane];
        const float xr0 = __shfl_sync(0xffffffffu, xl, r);
        const float xr8 = __shfl_sync(0xffffffffu, xl, r + 8);

        uint32_t h1f[4][4];
#pragma unroll
        for (int kk = 0; kk < 4; kk++) {
            h1f[kk][0] = tf32_bits(fmaxf(fmaf(xr0, w1v[kk * 2 + 0], b1v[kk * 2 + 0]), 0.f));
            h1f[kk][1] = tf32_bits(fmaxf(fmaf(xr8, w1v[kk * 2 + 0], b1v[kk * 2 + 0]), 0.f));
            h1f[kk][2] = tf32_bits(fmaxf(fmaf(xr0, w1v[kk * 2 + 1], b1v[kk * 2 + 1]), 0.f));
            h1f[kk][3] = tf32_bits(fmaxf(fmaf(xr8, w1v[kk * 2 + 1], b1v[kk * 2 + 1]), 0.f));
        }

        float c2[4][4];
#pragma unroll
        for (int nt = 0; nt < 4; nt++)
#pragma unroll
            for (int q = 0; q < 4; q++) c2[nt][q] = 0.f;
#pragma unroll
        for (int kk = 0; kk < 4; kk++)
#pragma unroll
            for (int nt = 0; nt < 4; nt++)
                mma_tf32(c2[nt][0], c2[nt][1], c2[nt][2], c2[nt][3],
                         h1f[kk][0], h1f[kk][1], h1f[kk][2], h1f[kk][3],
                         w2f[kk][nt][0], w2f[kk][nt][1]);

        uint32_t h2r[4][4];
#pragma unroll
        for (int nt = 0; nt < 4; nt++) {
            h2r[nt][0] = tf32_bits(fmaxf(c2[nt][0] + b2v[nt * 2 + 0], 0.f));
            h2r[nt][1] = tf32_bits(fmaxf(c2[nt][1] + b2v[nt * 2 + 1], 0.f));
            h2r[nt][2] = tf32_bits(fmaxf(c2[nt][2] + b2v[nt * 2 + 0], 0.f));
            h2r[nt][3] = tf32_bits(fmaxf(c2[nt][3] + b2v[nt * 2 + 1], 0.f));
        }

        uint32_t h2a[4][4];
#pragma unroll
        for (int kk = 0; kk < 4; kk++) {
            const uint32_t e0 = __shfl_sync(0xffffffffu, h2r[kk][0], L0);
            const uint32_t o0 = __shfl_sync(0xffffffffu, h2r[kk][1], L0);
            const uint32_t e8 = __shfl_sync(0xffffffffu, h2r[kk][2], L0);
            const uint32_t o8 = __shfl_sync(0xffffffffu, h2r[kk][3], L0);
            const uint32_t f0 = __shfl_sync(0xffffffffu, h2r[kk][0], L0 + 2);
            const uint32_t p0 = __shfl_sync(0xffffffffu, h2r[kk][1], L0 + 2);
            const uint32_t f8 = __shfl_sync(0xffffffffu, h2r[kk][2], L0 + 2);
            const uint32_t p8 = __shfl_sync(0xffffffffu, h2r[kk][3], L0 + 2);
            h2a[kk][0] = odd ? o0 : e0;
            h2a[kk][1] = odd ? o8 : e8;
            h2a[kk][2] = odd ? p0 : f0;
            h2a[kk][3] = odd ? p8 : f8;
        }

        float u[2][4];
#pragma unroll
        for (int nt = 0; nt < 2; nt++) {
            u[nt][0] = b3v[nt * 2 + 0];
            u[nt][1] = b3v[nt * 2 + 1];
            u[nt][2] = b3v[nt * 2 + 0];
            u[nt][3] = b3v[nt * 2 + 1];
        }
#pragma unroll
        for (int kk = 0; kk < 4; kk++)
#pragma unroll
            for (int nt = 0; nt < 2; nt++)
                mma_tf32(u[nt][0], u[nt][1], u[nt][2], u[nt][3],
                         h2a[kk][0], h2a[kk][1], h2a[kk][2], h2a[kk][3],
                         w3f[kk][nt][0], w3f[kk][nt][1]);

        const int lr0 = t * 16 + r;
#pragma unroll
        for (int nt = 0; nt < 2; nt++) {
            const int col = nt * 8 + 2 * c;
            atomicAdd(&acc_s[lr0 * 17 + col],           u[nt][0]);
            atomicAdd(&acc_s[lr0 * 17 + col + 1],       u[nt][1]);
            atomicAdd(&acc_s[(lr0 + 8) * 17 + col],     u[nt][2]);
            atomicAdd(&acc_s[(lr0 + 8) * 17 + col + 1], u[nt][3]);
        }
    }

    __syncthreads();
#pragma unroll
    for (int q = 0; q < 16; q++) {
        const int idx = q * 256 + tid;
        const int row = idx >> 4, col = idx & 15;
        atomicAdd(&uni_out[(size_t)(rowbase + row) * NOUT + col],
                  acc_s[row * 17 + col]);
    }
}

// ---------------------------------------------------------------------------
extern "C" void kernel_launch(void* const* d_in, const int* in_sizes, int n_in,
                              void* d_out, int out_size)
{
    const float* x   = (const float*)d_in[0];
    const float* W0  = (const float*)d_in[1];
    const float* b0  = (const float*)d_in[2];
    const float* W1  = (const float*)d_in[3];
    const float* b1  = (const float*)d_in[4];
    const float* W2  = (const float*)d_in[5];
    const float* b2  = (const float*)d_in[6];
    const float* uw1 = (const float*)d_in[7];
    const float* ub1 = (const float*)d_in[8];
    const float* uw2 = (const float*)d_in[9];
    const float* ub2 = (const float*)d_in[10];
    const float* uw3 = (const float*)d_in[11];
    const float* ub3 = (const float*)d_in[12];
    float* out = (float*)d_out;

    float *h0, *xr, *xt, *w0t, *w1t, *w2t, *uw2t, *uw3t;
    cudaGetSymbolAddress((void**)&h0, g_h0);
    cudaGetSymbolAddress((void**)&xr, g_x);
    cudaGetSymbolAddress((void**)&xt, g_xt);
    cudaGetSymbolAddress((void**)&w0t, g_w0t);
    cudaGetSymbolAddress((void**)&w1t, g_w1t);
    cudaGetSymbolAddress((void**)&w2t, g_w2t);
    cudaGetSymbolAddress((void**)&uw2t, g_uw2t);
    cudaGetSymbolAddress((void**)&uw3t, g_uw3t);

    cudaFuncSetAttribute(mma_gemm, cudaFuncAttributeMaxDynamicSharedMemorySize, GEMM_SMEM);
    cudaFuncSetAttribute(mma_gemm_out, cudaFuncAttributeMaxDynamicSharedMemorySize, GEMM_SMEM);

    // main-MLP front half first: slot 3 = GEMM0 (profiler capture target)
    cvt_x<<<(BATCH * NINP / 4 + 255) / 256, 256>>>(x, xr, BATCH * NINP / 4);   // 0
    {
        dim3 g0(HID / 32, NINP / 32);
        transpose_cvt<<<g0, 256>>>(W0, w0t, NINP, HID);                        // 1
        dim3 g1(HID / 32, HID / 32);
        transpose_cvt<<<g1, 256>>>(W1, w1t, HID, HID);                         // 2
    }
    {
        dim3 grid(HID / BN, BATCH / BM);
        mma_gemm<<<grid, 256, GEMM_SMEM>>>(xr, w0t, b0, h0, NINP, HID, 1, 1);  // 3
    }
    w2t_prep<<<NOUT * HID / 256, 256>>>(W2, w2t);                              // 4
    uni_w_prep<<<NINP, 256>>>(uw2, uw3, uw2t, uw3t);                           // 5
    {
        dim3 gx(NINP / 32, BATCH / 32);
        transpose_cvt<<<gx, 256>>>(x, xt, BATCH, NINP);                        // 6
    }
    zero_out<<<BATCH * NOUT / 256, 256>>>(out);                                // 7
    {
        dim3 grid(BATCH / 256, NINP / 8);
        uni_reg<<<grid, 256>>>(xt, uw1, ub1, uw2t, ub2, uw3t, ub3, out);       // 8
    }
    {
        dim3 grid(HID / BN, BATCH / BM);
        mma_gemm_out<<<grid, 256, GEMM_SMEM>>>(h0, w1t, b1, w2t, b2, out);     // 9
    }
}

// round 17
// speedup vs baseline: 1.0717x; 1.0193x over previous
#include <cuda_runtime.h>
#include <cstdint>

#define BATCH 16384
#define NINP  256
#define HID   1024
#define NOUT  16
#define UH    32

// ---------------------------------------------------------------------------
// Device scratch (no runtime allocation allowed)
// ---------------------------------------------------------------------------
__device__ float g_h0[BATCH * HID];
__device__ float g_x[BATCH * NINP];    // x pre-rounded to tf32 (main GEMM A)
__device__ float g_xt[NINP * BATCH];   // x^T, tf32-rounded (uni layer-1 input)
__device__ float g_w0t[HID * NINP];    // W0^T [HID][NINP], tf32-rounded
__device__ float g_w1t[HID * HID];     // W1^T, tf32-rounded
__device__ float g_w2t[NOUT * HID];    // W2^T [16][1024], tf32-rounded
__device__ float g_uw2t[NINP * UH * UH];    // per-feature w2^T [i][fo][fi], tf32
__device__ float g_uw3t[NINP * UH * NOUT];  // per-feature w3^T [i][fo][fi], tf32

// ---------------------------------------------------------------------------
// Helpers
// ---------------------------------------------------------------------------
__device__ __forceinline__ uint32_t smem_u32(const void* p) {
    uint32_t a;
    asm("{ .reg .u64 t; cvta.to.shared.u64 t, %1; cvt.u32.u64 %0, t; }"
        : "=r"(a) : "l"(p));
    return a;
}

// tf32 destination is a .b32 register (storage format), per PTX ISA.
__device__ __forceinline__ float to_tf32(float x) {
    uint32_t r;
    asm("cvt.rna.tf32.f32 %0, %1;" : "=r"(r) : "f"(x));
    return __uint_as_float(r);
}
__device__ __forceinline__ uint32_t tf32_bits(float x) {
    uint32_t r;
    asm("cvt.rna.tf32.f32 %0, %1;" : "=r"(r) : "f"(x));
    return r;
}

#define CP_ASYNC16(dst_u32, src_ptr) \
    asm volatile("cp.async.cg.shared.global [%0], [%1], 16;" \
        :: "r"(dst_u32), "l"(src_ptr))
#define CP_COMMIT() asm volatile("cp.async.commit_group;")
#define CP_WAIT(n)  asm volatile("cp.async.wait_group %0;" :: "n"(n))

__device__ __forceinline__ void mma_tf32(
    float& d0, float& d1, float& d2, float& d3,
    uint32_t a0, uint32_t a1, uint32_t a2, uint32_t a3,
    uint32_t b0, uint32_t b1)
{
    asm volatile(
        "mma.sync.aligned.m16n8k8.row.col.f32.tf32.tf32.f32 "
        "{%0,%1,%2,%3}, {%4,%5,%6,%7}, {%8,%9}, {%0,%1,%2,%3};"
        : "+f"(d0), "+f"(d1), "+f"(d2), "+f"(d3)
        : "r"(a0), "r"(a1), "r"(a2), "r"(a3), "r"(b0), "r"(b1));
}

// ---------------------------------------------------------------------------
// Shared GEMM config
// ---------------------------------------------------------------------------
#define BM 128
#define BN 256
#define BK 32
#define ASTR 36
#define AS_FLOATS (BM * ASTR)
#define BS_FLOATS (BN * ASTR)
#define STG_FLOATS (AS_FLOATS + BS_FLOATS)
#define GEMM_SMEM ((BN + 2 * STG_FLOATS) * 4)

// ---------------------------------------------------------------------------
// tf32 mma.sync GEMM (used for GEMM0; measured 77.7us)
// ---------------------------------------------------------------------------
__global__ void __launch_bounds__(256, 1) mma_gemm(
    const float* __restrict__ A, const float* __restrict__ BT,
    const float* __restrict__ bias, float* __restrict__ C,
    int K, int Ntot, int relu, int roundout)
{
    extern __shared__ float sm[];
    float* bias_s = sm;
    float* stage0 = sm + BN;
    const uint32_t stage0_u32 = smem_u32(stage0);

    const int tid = threadIdx.x;
    const int lane = tid & 31;
    const int wid = tid >> 5;
    const int wr = wid >> 2;
    const int wc = wid & 3;
    const int m0 = blockIdx.y * BM;
    const int n0 = blockIdx.x * BN;

    if (tid < BN) bias_s[tid] = bias[n0 + tid];

    const int r = lane >> 2;
    const int c = lane & 3;

    float acc[4][8][4];
#pragma unroll
    for (int mt = 0; mt < 4; mt++)
#pragma unroll
        for (int nt = 0; nt < 8; nt++)
#pragma unroll
            for (int j = 0; j < 4; j++) acc[mt][nt][j] = 0.f;

    const int T = K / BK;

    auto issue = [&](int t) {
        const uint32_t su = stage0_u32 + (uint32_t)((t & 1) * STG_FLOATS) * 4u;
#pragma unroll
        for (int i = 0; i < 4; i++) {
            const int q = tid + i * 256;
            const int row = q >> 3, qq = q & 7;
            CP_ASYNC16(su + (uint32_t)(row * ASTR + qq * 4) * 4u,
                       A + (size_t)(m0 + row) * K + t * BK + qq * 4);
        }
        const uint32_t bu = su + AS_FLOATS * 4u;
#pragma unroll
        for (int i = 0; i < 8; i++) {
            const int q = tid + i * 256;
            const int row = q >> 3, qq = q & 7;
            CP_ASYNC16(bu + (uint32_t)(row * ASTR + qq * 4) * 4u,
                       BT + (size_t)(n0 + row) * K + t * BK + qq * 4);
        }
    };

    issue(0);
    CP_COMMIT();

    for (int t = 0; t < T; t++) {
        if (t + 1 < T) {
            issue(t + 1);
            CP_COMMIT();
            CP_WAIT(1);
        } else {
            CP_WAIT(0);
        }
        __syncthreads();

        const float* As = stage0 + (t & 1) * STG_FLOATS;
        const float* Bs = As + AS_FLOATS;

#pragma unroll
        for (int kk = 0; kk < 4; kk++) {
            uint32_t af[4][4];
#pragma unroll
            for (int mt = 0; mt < 4; mt++) {
                const int mb = wr * 64 + mt * 16;
                af[mt][0] = *(const uint32_t*)&As[(mb + r) * ASTR + kk * 8 + c];
                af[mt][1] = *(const uint32_t*)&As[(mb + r + 8) * ASTR + kk * 8 + c];
                af[mt][2] = *(const uint32_t*)&As[(mb + r) * ASTR + kk * 8 + c + 4];
                af[mt][3] = *(const uint32_t*)&As[(mb + r + 8) * ASTR + kk * 8 + c + 4];
            }
            uint32_t bf[8][2];
#pragma unroll
            for (int nt = 0; nt < 8; nt++) {
                const int bn = wc * 64 + nt * 8 + r;
                bf[nt][0] = *(const uint32_t*)&Bs[bn * ASTR + kk * 8 + c];
                bf[nt][1] = *(const uint32_t*)&Bs[bn * ASTR + kk * 8 + c + 4];
            }
#pragma unroll
            for (int mt = 0; mt < 4; mt++)
#pragma unroll
                for (int nt = 0; nt < 8; nt++)
                    mma_tf32(acc[mt][nt][0], acc[mt][nt][1],
                             acc[mt][nt][2], acc[mt][nt][3],
                             af[mt][0], af[mt][1], af[mt][2], af[mt][3],
                             bf[nt][0], bf[nt][1]);
        }
        __syncthreads();
    }

#pragma unroll
    for (int mt = 0; mt < 4; mt++) {
        const int row0 = m0 + wr * 64 + mt * 16 + r;
#pragma unroll
        for (int nt = 0; nt < 8; nt++) {
            const int col = n0 + wc * 64 + nt * 8 + c * 2;
            const float bx = bias_s[wc * 64 + nt * 8 + c * 2];
            const float by = bias_s[wc * 64 + nt * 8 + c * 2 + 1];
            float v0 = acc[mt][nt][0] + bx;
            float v1 = acc[mt][nt][1] + by;
            float v2 = acc[mt][nt][2] + bx;
            float v3 = acc[mt][nt][3] + by;
            if (relu) {
                v0 = fmaxf(v0, 0.f); v1 = fmaxf(v1, 0.f);
                v2 = fmaxf(v2, 0.f); v3 = fmaxf(v3, 0.f);
            }
            if (roundout) {
                v0 = to_tf32(v0); v1 = to_tf32(v1);
                v2 = to_tf32(v2); v3 = to_tf32(v3);
            }
            *(float2*)&C[(size_t)row0 * Ntot + col] = make_float2(v0, v1);
            *(float2*)&C[(size_t)(row0 + 8) * Ntot + col] = make_float2(v2, v3);
        }
    }
}

// ---------------------------------------------------------------------------
// GEMM1 with FUSED output layer. W2T fragments hoisted to registers (loaded
// once, reused across all 4 mt epilogue tiles).
// ---------------------------------------------------------------------------
__global__ void __launch_bounds__(256, 1) mma_gemm_out(
    const float* __restrict__ A, const float* __restrict__ BT,
    const float* __restrict__ bias, const float* __restrict__ W2T,
    const float* __restrict__ b2, float* __restrict__ out)
{
    extern __shared__ float sm[];
    float* bias_s = sm;
    float* stage0 = sm + BN;
    const uint32_t stage0_u32 = smem_u32(stage0);

    const int tid = threadIdx.x;
    const int lane = tid & 31;
    const int wid = tid >> 5;
    const int wr = wid >> 2;
    const int wc = wid & 3;
    const int m0 = blockIdx.y * BM;
    const int n0 = blockIdx.x * BN;
    const int K = HID;

    if (tid < BN) bias_s[tid] = bias[n0 + tid];

    const int r = lane >> 2;
    const int c = lane & 3;

    float acc[4][8][4];
#pragma unroll
    for (int mt = 0; mt < 4; mt++)
#pragma unroll
        for (int nt = 0; nt < 8; nt++)
#pragma unroll
            for (int j = 0; j < 4; j++) acc[mt][nt][j] = 0.f;

    const int T = K / BK;

    auto issue = [&](int t) {
        const uint32_t su = stage0_u32 + (uint32_t)((t & 1) * STG_FLOATS) * 4u;
#pragma unroll
        for (int i = 0; i < 4; i++) {
            const int q = tid + i * 256;
            const int row = q >> 3, qq = q & 7;
            CP_ASYNC16(su + (uint32_t)(row * ASTR + qq * 4) * 4u,
                       A + (size_t)(m0 + row) * K + t * BK + qq * 4);
        }
        const uint32_t bu = su + AS_FLOATS * 4u;
#pragma unroll
        for (int i = 0; i < 8; i++) {
            const int q = tid + i * 256;
            const int row = q >> 3, qq = q & 7;
            CP_ASYNC16(bu + (uint32_t)(row * ASTR + qq * 4) * 4u,
                       BT + (size_t)(n0 + row) * K + t * BK + qq * 4);
        }
    };

    issue(0);
    CP_COMMIT();

    for (int t = 0; t < T; t++) {
        if (t + 1 < T) {
            issue(t + 1);
            CP_COMMIT();
            CP_WAIT(1);
        } else {
            CP_WAIT(0);
        }
        __syncthreads();

        const float* As = stage0 + (t & 1) * STG_FLOATS;
        const float* Bs = As + AS_FLOATS;

#pragma unroll
        for (int kk = 0; kk < 4; kk++) {
            uint32_t af[4][4];
#pragma unroll
            for (int mt = 0; mt < 4; mt++) {
                const int mb = wr * 64 + mt * 16;
                af[mt][0] = *(const uint32_t*)&As[(mb + r) * ASTR + kk * 8 + c];
                af[mt][1] = *(const uint32_t*)&As[(mb + r + 8) * ASTR + kk * 8 + c];
                af[mt][2] = *(const uint32_t*)&As[(mb + r) * ASTR + kk * 8 + c + 4];
                af[mt][3] = *(const uint32_t*)&As[(mb + r + 8) * ASTR + kk * 8 + c + 4];
            }
            uint32_t bf[8][2];
#pragma unroll
            for (int nt = 0; nt < 8; nt++) {
                const int bn = wc * 64 + nt * 8 + r;
                bf[nt][0] = *(const uint32_t*)&Bs[bn * ASTR + kk * 8 + c];
                bf[nt][1] = *(const uint32_t*)&Bs[bn * ASTR + kk * 8 + c + 4];
            }
#pragma unroll
            for (int mt = 0; mt < 4; mt++)
#pragma unroll
                for (int nt = 0; nt < 8; nt++)
                    mma_tf32(acc[mt][nt][0], acc[mt][nt][1],
                             acc[mt][nt][2], acc[mt][nt][3],
                             af[mt][0], af[mt][1], af[mt][2], af[mt][3],
                             bf[nt][0], bf[nt][1]);
        }
        __syncthreads();
    }

    // ---- fused output epilogue ----
    // Hoisted W2T fragments (reused across all 4 mt tiles).
    const int wcol0 = n0 + wc * 64;
    uint32_t w2f[8][2][2];
#pragma unroll
    for (int kk = 0; kk < 8; kk++)
#pragma unroll
        for (int nt2 = 0; nt2 < 2; nt2++) {
            w2f[kk][nt2][0] = __float_as_uint(
                W2T[(size_t)(nt2 * 8 + r) * HID + wcol0 + kk * 8 + c]);
            w2f[kk][nt2][1] = __float_as_uint(
                W2T[(size_t)(nt2 * 8 + r) * HID + wcol0 + kk * 8 + c + 4]);
        }

    float* ws = stage0 + wid * (16 * 68);            // per-warp 16x68 strip
    const bool addb = (blockIdx.x == 0 && wc == 0);

#pragma unroll
    for (int mt = 0; mt < 4; mt++) {
#pragma unroll
        for (int nt = 0; nt < 8; nt++) {
            const int j = nt * 8 + 2 * c;
            const float bx = bias_s[wc * 64 + j];
            const float by = bias_s[wc * 64 + j + 1];
            const float v0 = to_tf32(fmaxf(acc[mt][nt][0] + bx, 0.f));
            const float v1 = to_tf32(fmaxf(acc[mt][nt][1] + by, 0.f));
            const float v2 = to_tf32(fmaxf(acc[mt][nt][2] + bx, 0.f));
            const float v3 = to_tf32(fmaxf(acc[mt][nt][3] + by, 0.f));
            *(float2*)&ws[r * 68 + j] = make_float2(v0, v1);
            *(float2*)&ws[(r + 8) * 68 + j] = make_float2(v2, v3);
        }
        __syncwarp(0xffffffffu);

        float po[2][4];
#pragma unroll
        for (int nt2 = 0; nt2 < 2; nt2++)
#pragma unroll
            for (int q = 0; q < 4; q++) po[nt2][q] = 0.f;

#pragma unroll
        for (int kk = 0; kk < 8; kk++) {
            const uint32_t a0 = *(const uint32_t*)&ws[r * 68 + kk * 8 + c];
            const uint32_t a1 = *(const uint32_t*)&ws[(r + 8) * 68 + kk * 8 + c];
            const uint32_t a2 = *(const uint32_t*)&ws[r * 68 + kk * 8 + c + 4];
            const uint32_t a3 = *(const uint32_t*)&ws[(r + 8) * 68 + kk * 8 + c + 4];
#pragma unroll
            for (int nt2 = 0; nt2 < 2; nt2++)
                mma_tf32(po[nt2][0], po[nt2][1], po[nt2][2], po[nt2][3],
                         a0, a1, a2, a3, w2f[kk][nt2][0], w2f[kk][nt2][1]);
        }
        __syncwarp(0xffffffffu);     // strip reused next mt

        const int row0 = m0 + wr * 64 + mt * 16 + r;
#pragma unroll
        for (int nt2 = 0; nt2 < 2; nt2++) {
            const int col = nt2 * 8 + 2 * c;
            const float bx = addb ? b2[col] : 0.f;
            const float by = addb ? b2[col + 1] : 0.f;
            atomicAdd(&out[(size_t)row0 * NOUT + col],           po[nt2][0] + bx);
            atomicAdd(&out[(size_t)row0 * NOUT + col + 1],       po[nt2][1] + by);
            atomicAdd(&out[(size_t)(row0 + 8) * NOUT + col],     po[nt2][2] + bx);
            atomicAdd(&out[(size_t)(row0 + 8) * NOUT + col + 1], po[nt2][3] + by);
        }
    }
}

// ---------------------------------------------------------------------------
// prep_all: all preprocessing in ONE kernel (block-range dispatch) so that
// launch slot 3 lands on mma_gemm_out for the profiler.
// ---------------------------------------------------------------------------
#define PB_CVTX 4096                          // x -> xr (tf32), float4
#define PB_W0T  256                           // W0 -> w0t  (tiles 32x8)
#define PB_W1T  1024                          // W1 -> w1t  (tiles 32x32)
#define PB_XT   4096                          // x  -> xt   (tiles 8x512)
#define PB_W2T  64                            // W2 -> w2t
#define PB_UNIW 256                           // uni weights
#define PB_ZERO 1024                          // zero out
#define PREP_BLOCKS (PB_CVTX + PB_W0T + PB_W1T + PB_XT + PB_W2T + PB_UNIW + PB_ZERO)

__device__ __forceinline__ void transpose_tile(
    const float* __restrict__ W, float* __restrict__ WT,
    int K, int N, int bid2, int tiles_x, float t[32][33], int tid)
{
    const int bx = (bid2 % tiles_x) * 32;
    const int by = (bid2 / tiles_x) * 32;
    const int x = tid & 31;
    const int y = tid >> 5;
#pragma unroll
    for (int i = 0; i < 32; i += 8)
        t[y + i][x] = to_tf32(W[(size_t)(by + y + i) * N + bx + x]);
    __syncthreads();
#pragma unroll
    for (int i = 0; i < 32; i += 8)
        WT[(size_t)(bx + y + i) * K + by + x] = t[x][y + i];
}

__global__ void __launch_bounds__(256) prep_all(
    const float* __restrict__ x,
    const float* __restrict__ W0, const float* __restrict__ W1,
    const float* __restrict__ W2,
    const float* __restrict__ uw2, const float* __restrict__ uw3,
    float* __restrict__ xr, float* __restrict__ w0t, float* __restrict__ w1t,
    float* __restrict__ w2t, float* __restrict__ xt,
    float* __restrict__ uw2t, float* __restrict__ uw3t,
    float* __restrict__ out)
{
    __shared__ float t[32][33];
    __shared__ float t3[32][17];
    const int tid = threadIdx.x;
    int bid = blockIdx.x;

    if (bid < PB_CVTX) {                       // x -> xr
        const int i = bid * 256 + tid;
        float4 v = ((const float4*)x)[i];
        v.x = to_tf32(v.x); v.y = to_tf32(v.y);
        v.z = to_tf32(v.z); v.w = to_tf32(v.w);
        ((float4*)xr)[i] = v;
        return;
    }
    bid -= PB_CVTX;
    if (bid < PB_W0T) {                        // W0[K=256][N=1024] -> w0t
        transpose_tile(W0, w0t, NINP, HID, bid, HID / 32, t, tid);
        return;
    }
    bid -= PB_W0T;
    if (bid < PB_W1T) {                        // W1 -> w1t
        transpose_tile(W1, w1t, HID, HID, bid, HID / 32, t, tid);
        return;
    }
    bid -= PB_W1T;
    if (bid < PB_XT) {                         // x[B][256] -> xt[256][B]
        transpose_tile(x, xt, BATCH, NINP, bid, NINP / 32, t, tid);
        return;
    }
    bid -= PB_XT;
    if (bid < PB_W2T) {                        // W2 -> w2t
        const int idx = bid * 256 + tid;
        const int k = idx >> 4, o = idx & 15;
        w2t[(size_t)o * HID + k] = to_tf32(W2[(size_t)k * NOUT + o]);
        return;
    }
    bid -= PB_W2T;
    if (bid < PB_UNIW) {                       // uni weights transpose
        const int i = bid;
        {
            float4 v = ((const float4*)(uw2 + (size_t)i * UH * UH))[tid];
            const int fi = tid >> 3;
            const int fo = (tid & 7) * 4;
            t[fi][fo + 0] = to_tf32(v.x);
            t[fi][fo + 1] = to_tf32(v.y);
            t[fi][fo + 2] = to_tf32(v.z);
            t[fi][fo + 3] = to_tf32(v.w);
        }
        {
            float2 v = ((const float2*)(uw3 + (size_t)i * UH * NOUT))[tid];
            const int fi = tid >> 3;
            const int fo = (tid & 7) * 2;
            t3[fi][fo + 0] = to_tf32(v.x);
            t3[fi][fo + 1] = to_tf32(v.y);
        }
        __syncthreads();
        {
            const int fo = tid >> 3;
            const int fi = (tid & 7) * 4;
            float4 o;
            o.x = t[fi + 0][fo]; o.y = t[fi + 1][fo];
            o.z = t[fi + 2][fo]; o.w = t[fi + 3][fo];
            ((float4*)(uw2t + (size_t)i * UH * UH))[tid] = o;
        }
        {
            const int fo = tid >> 4;
            const int fi = (tid & 15) * 2;
            float2 o;
            o.x = t3[fi + 0][fo]; o.y = t3[fi + 1][fo];
            ((float2*)(uw3t + (size_t)i * NOUT * UH))[tid] = o;
        }
        return;
    }
    bid -= PB_UNIW;
    // zero out
    out[bid * 256 + tid] = 0.f;
}

// ---------------------------------------------------------------------------
// Register-resident uni MLPs (measured 209.7us); merges directly into out.
// ---------------------------------------------------------------------------
__global__ void __launch_bounds__(256) uni_reg(
    const float* __restrict__ xt,
    const float* __restrict__ uw1, const float* __restrict__ ub1,
    const float* __restrict__ uw2t, const float* __restrict__ ub2,
    const float* __restrict__ uw3t, const float* __restrict__ ub3,
    float* __restrict__ uni_out)
{
    __shared__ float acc_s[256 * 17];

    const int tid = threadIdx.x;
    const int lane = tid & 31;
    const int w = tid >> 5;
    const int r = lane >> 2;
    const int c = lane & 3;
    const int i = blockIdx.y * 8 + w;
    const int rowbase = blockIdx.x * 256;

#pragma unroll
    for (int q = 0; q < 17; q++) acc_s[q * 256 + tid] = 0.f;
    __syncthreads();

    uint32_t w2f[4][4][2];
#pragma unroll
    for (int kk = 0; kk < 4; kk++)
#pragma unroll
        for (int nt = 0; nt < 4; nt++) {
            const float* p = uw2t + (size_t)i * 1024 + (nt * 8 + r) * 32 + kk * 8 + c;
            w2f[kk][nt][0] = __float_as_uint(p[0]);
            w2f[kk][nt][1] = __float_as_uint(p[4]);
        }
    uint32_t w3f[4][2][2];
#pragma unroll
    for (int kk = 0; kk < 4; kk++)
#pragma unroll
        for (int nt = 0; nt < 2; nt++) {
            const float* p = uw3t + (size_t)i * 512 + (nt * 8 + r) * 32 + kk * 8 + c;
            w3f[kk][nt][0] = __float_as_uint(p[0]);
            w3f[kk][nt][1] = __float_as_uint(p[4]);
        }
    float w1v[8], b1v[8];
#pragma unroll
    for (int kk = 0; kk < 4; kk++) {
        w1v[kk * 2 + 0] = uw1[i * 32 + kk * 8 + c];
        w1v[kk * 2 + 1] = uw1[i * 32 + kk * 8 + c + 4];
        b1v[kk * 2 + 0] = ub1[i * 32 + kk * 8 + c];
        b1v[kk * 2 + 1] = ub1[i * 32 + kk * 8 + c + 4];
    }
    float b2v[8];
#pragma unroll
    for (int nt = 0; nt < 4; nt++) {
        b2v[nt * 2 + 0] = ub2[i * 32 + nt * 8 + 2 * c];
        b2v[nt * 2 + 1] = ub2[i * 32 + nt * 8 + 2 * c + 1];
    }
    float b3v[4];
#pragma unroll
    for (int nt = 0; nt < 2; nt++) {
        b3v[nt * 2 + 0] = ub3[i * 16 + nt * 8 + 2 * c];
        b3v[nt * 2 + 1] = ub3[i * 16 + nt * 8 + 2 * c + 1];
    }

    const int L0 = r * 4 + (c >> 1);
    const bool odd = (c & 1) != 0;

    for (int t = 0; t < 16; t++) {
        const int rb = rowbase + t * 16;

        float xl = 0.f;
        if (lane < 16) xl = xt[(size_t)i * BATCH + rb + lane];
        const float xr0 = __shfl_sync(0xffffffffu, xl, r);
        const float xr8 = __shfl_sync(0xffffffffu, xl, r + 8);

        uint32_t h1f[4][4];
#pragma unroll
        for (int kk = 0; kk < 4; kk++) {
            h1f[kk][0] = tf32_bits(fmaxf(fmaf(xr0, w1v[kk * 2 + 0], b1v[kk * 2 + 0]), 0.f));
            h1f[kk][1] = tf32_bits(fmaxf(fmaf(xr8, w1v[kk * 2 + 0], b1v[kk * 2 + 0]), 0.f));
            h1f[kk][2] = tf32_bits(fmaxf(fmaf(xr0, w1v[kk * 2 + 1], b1v[kk * 2 + 1]), 0.f));
            h1f[kk][3] = tf32_bits(fmaxf(fmaf(xr8, w1v[kk * 2 + 1], b1v[kk * 2 + 1]), 0.f));
        }

        float c2[4][4];
#pragma unroll
        for (int nt = 0; nt < 4; nt++)
#pragma unroll
            for (int q = 0; q < 4; q++) c2[nt][q] = 0.f;
#pragma unroll
        for (int kk = 0; kk < 4; kk++)
#pragma unroll
            for (int nt = 0; nt < 4; nt++)
                mma_tf32(c2[nt][0], c2[nt][1], c2[nt][2], c2[nt][3],
                         h1f[kk][0], h1f[kk][1], h1f[kk][2], h1f[kk][3],
                         w2f[kk][nt][0], w2f[kk][nt][1]);

        uint32_t h2r[4][4];
#pragma unroll
        for (int nt = 0; nt < 4; nt++) {
            h2r[nt][0] = tf32_bits(fmaxf(c2[nt][0] + b2v[nt * 2 + 0], 0.f));
            h2r[nt][1] = tf32_bits(fmaxf(c2[nt][1] + b2v[nt * 2 + 1], 0.f));
            h2r[nt][2] = tf32_bits(fmaxf(c2[nt][2] + b2v[nt * 2 + 0], 0.f));
            h2r[nt][3] = tf32_bits(fmaxf(c2[nt][3] + b2v[nt * 2 + 1], 0.f));
        }

        uint32_t h2a[4][4];
#pragma unroll
        for (int kk = 0; kk < 4; kk++) {
            const uint32_t e0 = __shfl_sync(0xffffffffu, h2r[kk][0], L0);
            const uint32_t o0 = __shfl_sync(0xffffffffu, h2r[kk][1], L0);
            const uint32_t e8 = __shfl_sync(0xffffffffu, h2r[kk][2], L0);
            const uint32_t o8 = __shfl_sync(0xffffffffu, h2r[kk][3], L0);
            const uint32_t f0 = __shfl_sync(0xffffffffu, h2r[kk][0], L0 + 2);
            const uint32_t p0 = __shfl_sync(0xffffffffu, h2r[kk][1], L0 + 2);
            const uint32_t f8 = __shfl_sync(0xffffffffu, h2r[kk][2], L0 + 2);
            const uint32_t p8 = __shfl_sync(0xffffffffu, h2r[kk][3], L0 + 2);
            h2a[kk][0] = odd ? o0 : e0;
            h2a[kk][1] = odd ? o8 : e8;
            h2a[kk][2] = odd ? p0 : f0;
            h2a[kk][3] = odd ? p8 : f8;
        }

        float u[2][4];
#pragma unroll
        for (int nt = 0; nt < 2; nt++) {
            u[nt][0] = b3v[nt * 2 + 0];
            u[nt][1] = b3v[nt * 2 + 1];
            u[nt][2] = b3v[nt * 2 + 0];
            u[nt][3] = b3v[nt * 2 + 1];
        }
#pragma unroll
        for (int kk = 0; kk < 4; kk++)
#pragma unroll
            for (int nt = 0; nt < 2; nt++)
                mma_tf32(u[nt][0], u[nt][1], u[nt][2], u[nt][3],
                         h2a[kk][0], h2a[kk][1], h2a[kk][2], h2a[kk][3],
                         w3f[kk][nt][0], w3f[kk][nt][1]);

        const int lr0 = t * 16 + r;
#pragma unroll
        for (int nt = 0; nt < 2; nt++) {
            const int col = nt * 8 + 2 * c;
            atomicAdd(&acc_s[lr0 * 17 + col],           u[nt][0]);
            atomicAdd(&acc_s[lr0 * 17 + col + 1],       u[nt][1]);
            atomicAdd(&acc_s[(lr0 + 8) * 17 + col],     u[nt][2]);
            atomicAdd(&acc_s[(lr0 + 8) * 17 + col + 1], u[nt][3]);
        }
    }

    __syncthreads();
#pragma unroll
    for (int q = 0; q < 16; q++) {
        const int idx = q * 256 + tid;
        const int row = idx >> 4, col = idx & 15;
        atomicAdd(&uni_out[(size_t)(rowbase + row) * NOUT + col],
                  acc_s[row * 17 + col]);
    }
}

// ---------------------------------------------------------------------------
extern "C" void kernel_launch(void* const* d_in, const int* in_sizes, int n_in,
                              void* d_out, int out_size)
{
    const float* x   = (const float*)d_in[0];
    const float* W0  = (const float*)d_in[1];
    const float* b0  = (const float*)d_in[2];
    const float* W1  = (const float*)d_in[3];
    const float* b1  = (const float*)d_in[4];
    const float* W2  = (const float*)d_in[5];
    const float* b2  = (const float*)d_in[6];
    const float* uw1 = (const float*)d_in[7];
    const float* ub1 = (const float*)d_in[8];
    const float* uw2 = (const float*)d_in[9];
    const float* ub2 = (const float*)d_in[10];
    const float* uw3 = (const float*)d_in[11];
    const float* ub3 = (const float*)d_in[12];
    float* out = (float*)d_out;

    float *h0, *xr, *xt, *w0t, *w1t, *w2t, *uw2t, *uw3t;
    cudaGetSymbolAddress((void**)&h0, g_h0);
    cudaGetSymbolAddress((void**)&xr, g_x);
    cudaGetSymbolAddress((void**)&xt, g_xt);
    cudaGetSymbolAddress((void**)&w0t, g_w0t);
    cudaGetSymbolAddress((void**)&w1t, g_w1t);
    cudaGetSymbolAddress((void**)&w2t, g_w2t);
    cudaGetSymbolAddress((void**)&uw2t, g_uw2t);
    cudaGetSymbolAddress((void**)&uw3t, g_uw3t);

    cudaFuncSetAttribute(mma_gemm, cudaFuncAttributeMaxDynamicSharedMemorySize, GEMM_SMEM);
    cudaFuncSetAttribute(mma_gemm_out, cudaFuncAttributeMaxDynamicSharedMemorySize, GEMM_SMEM);

    // slot 0: all prep (incl. zeroing out)
    prep_all<<<PREP_BLOCKS, 256>>>(x, W0, W1, W2, uw2, uw3,
                                   xr, w0t, w1t, w2t, xt, uw2t, uw3t, out);
    // slot 1: GEMM0
    {
        dim3 grid(HID / BN, BATCH / BM);
        mma_gemm<<<grid, 256, GEMM_SMEM>>>(xr, w0t, b0, h0, NINP, HID, 1, 1);
    }
    // slot 2: uni MLPs -> out (atomic)
    {
        dim3 grid(BATCH / 256, NINP / 8);
        uni_reg<<<grid, 256>>>(xt, uw1, ub1, uw2t, ub2, uw3t, ub3, out);
    }
    // slot 3: GEMM1 + fused output layer (profiler capture slot)
    {
        dim3 grid(HID / BN, BATCH / BM);
        mma_gemm_out<<<grid, 256, GEMM_SMEM>>>(h0, w1t, b1, w2t, b2, out);
    }
}